// round 14
// baseline (speedup 1.0000x reference)
#include <cuda_runtime.h>
#include <float.h>

#define PH 7
#define PW 7
#define BD 2
#define ND 96
#define HD 64
#define WD 64
#define CD 128

#define NROI (BD * ND)              // 192
#define UN 8                        // prefetch depth (MLP)

__device__ __forceinline__ void fmax4(float4& a, const float4& v) {
    a.x = fmaxf(a.x, v.x);
    a.y = fmaxf(a.y, v.y);
    a.z = fmaxf(a.z, v.z);
    a.w = fmaxf(a.w, v.w);
}

// 16 CTAs per ROI:
//   slot 0..8  (A): 4 interior bins per CTA (warp-per-bin, <=25 px)
//   slot 9..14 (B): 2 edge bins per CTA, 2 warps each (long-axis halves, <=25 px)
//   slot 15    (C): corner bin, 4 warps (2x2 quadrants, <=25 px)
__global__ void __launch_bounds__(128)
roipool_kernel(const float* __restrict__ fmap,
               const float* __restrict__ rois,
               float* __restrict__ out) {
    const int warp = threadIdx.x >> 5;
    const int lane = threadIdx.x & 31;
    const int roi  = blockIdx.x >> 4;
    const int slot = blockIdx.x & 15;
    const int b    = roi / ND;

    // roi = [x_center, y_center, width, height]
    const float4 r4 = __ldg((const float4*)(rois) + roi);

    // y axis (yc, hh)
    const float halfh = floorf(r4.w * 0.5f);
    const int ys   = (int)(r4.y - halfh);
    const int lenh = (int)(r4.y + halfh) - ys;
    const int sth  = max(lenh / PH, 1);
    // x axis (xc, ww)
    const float halfw = floorf(r4.z * 0.5f);
    const int xs   = (int)(r4.x - halfw);
    const int lenw = (int)(r4.x + halfw) - xs;
    const int stw  = max(lenw / PW, 1);

    int ph, pw;
    int split2 = 0, half = 0;        // B: split along long axis
    int splitx = 0;                  // B: 1 = split x (pw==6 bins), 0 = split y
    int combine = 0;                 // 0=A, 2=B, 4=C

    if (slot < 9) {
        const int bi = slot * 4 + warp;   // 0..35
        ph = bi / 6; pw = bi % 6;
    } else if (slot < 15) {
        const int e = (slot - 9) * 2 + (warp >> 1);   // 0..11
        half = warp & 1;
        if (e < 6) { ph = e; pw = 6; splitx = 1; }
        else       { ph = 6; pw = e - 6; splitx = 0; }
        split2 = 1; combine = 2;
    } else {
        ph = 6; pw = 6; combine = 4;
    }

    // bin ranges (clamped)
    int y0 = max(ys + ph * sth, 0);
    int y1 = min(ys + ((ph == PH - 1) ? lenh : (ph + 1) * sth), HD);
    int x0 = max(xs + pw * stw, 0);
    int x1 = min(xs + ((pw == PW - 1) ? lenw : (pw + 1) * stw), WD);

    if (split2) {
        if (splitx) { const int m = x0 + ((x1 - x0) >> 1); if (half) x0 = m; else x1 = m; }
        else        { const int m = y0 + ((y1 - y0) >> 1); if (half) y0 = m; else y1 = m; }
    } else if (combine == 4) {
        const int my = y0 + ((y1 - y0) >> 1);
        const int mx = x0 + ((x1 - x0) >> 1);
        if (warp & 2) y0 = my; else y1 = my;
        if (warp & 1) x0 = mx; else x1 = mx;
    }

    const int nx   = x1 - x0;
    const int npix = (y1 - y0) * nx;   // may be 0 for degenerate piece

    const float4 neg4 = make_float4(-FLT_MAX, -FLT_MAX, -FLT_MAX, -FLT_MAX);
    float4 acc = neg4;

    // lane = 4-channel group; incremental pointer walk, UN loads in flight.
    // ALL batches are pipelined: the final partial batch predicates off the
    // out-of-range loads (and their pointer advances) instead of falling back
    // to a serial one-at-a-time remainder loop.
    const float4* p = (const float4*)(fmap + ((size_t)b * HD) * WD * CD)
                      + (y0 * WD + x0) * (CD / 4) + lane;
    const int rowskip = (WD - nx) * (CD / 4);
    int xi = 0;

#define ADV { p += (CD / 4); if (++xi == nx) { xi = 0; p += rowskip; } }

    float4 buf[UN];
    for (int i = 0; i < npix; i += UN) {
        #pragma unroll
        for (int k = 0; k < UN; k++) {
            if (i + k < npix) { buf[k] = __ldg(p); ADV }
            else              { buf[k] = neg4; }
        }
        #pragma unroll
        for (int k = 0; k < UN; k++) fmax4(acc, buf[k]);
    }

    const int bin = (roi * PH + ph) * PW + pw;

    if (combine == 0) {
        ((float4*)out)[(size_t)bin * 32 + lane] = acc;
    } else {
        __shared__ float4 smax[4][32];
        smax[warp][lane] = acc;
        __syncthreads();
        if (combine == 4) {
            if (warp == 0) {
                float4 a = smax[0][lane];
                fmax4(a, smax[1][lane]);
                fmax4(a, smax[2][lane]);
                fmax4(a, smax[3][lane]);
                ((float4*)out)[(size_t)bin * 32 + lane] = a;
            }
        } else {
            if ((warp & 1) == 0) {
                float4 a = smax[warp][lane];
                fmax4(a, smax[warp + 1][lane]);
                ((float4*)out)[(size_t)bin * 32 + lane] = a;
            }
        }
    }
}

extern "C" void kernel_launch(void* const* d_in, const int* in_sizes, int n_in,
                              void* d_out, int out_size) {
    const float* fmap = (const float*)d_in[0];
    const float* rois = (const float*)d_in[1];
    float* out = (float*)d_out;
    roipool_kernel<<<NROI * 16, 128>>>(fmap, rois, out);
}

// round 15
// speedup vs baseline: 1.0532x; 1.0532x over previous
#include <cuda_runtime.h>
#include <float.h>

#define PH 7
#define PW 7
#define BD 2
#define ND 96
#define HD 64
#define WD 64
#define CD 128

#define NROI (BD * ND)              // 192
#define UN 8                        // prefetch depth (MLP)

__device__ __forceinline__ void fmax4(float4& a, const float4& v) {
    a.x = fmaxf(a.x, v.x);
    a.y = fmaxf(a.y, v.y);
    a.z = fmaxf(a.z, v.z);
    a.w = fmaxf(a.w, v.w);
}

// 16 CTAs per ROI:
//   slot 0..8  (A): 4 interior bins per CTA (warp-per-bin, <=25 px)
//   slot 9..14 (B): 2 edge bins per CTA, 2 warps each (long-axis halves, <=25 px)
//   slot 15    (C): corner bin, 4 warps (2x2 quadrants, <=25 px)
__global__ void __launch_bounds__(128)
roipool_kernel(const float* __restrict__ fmap,
               const float* __restrict__ rois,
               float* __restrict__ out) {
    const int warp = threadIdx.x >> 5;
    const int lane = threadIdx.x & 31;
    const int roi  = blockIdx.x >> 4;
    const int slot = blockIdx.x & 15;
    const int b    = roi / ND;

    // roi = [x_center, y_center, width, height]
    const float4 r4 = __ldg((const float4*)(rois) + roi);

    // y axis (yc, hh)
    const float halfh = floorf(r4.w * 0.5f);
    const int ys   = (int)(r4.y - halfh);
    const int lenh = (int)(r4.y + halfh) - ys;
    const int sth  = max(lenh / PH, 1);
    // x axis (xc, ww)
    const float halfw = floorf(r4.z * 0.5f);
    const int xs   = (int)(r4.x - halfw);
    const int lenw = (int)(r4.x + halfw) - xs;
    const int stw  = max(lenw / PW, 1);

    int ph, pw;
    int split2 = 0, half = 0;        // B: split along long axis
    int splitx = 0;                  // B: 1 = split x (pw==6 bins), 0 = split y
    int combine = 0;                 // 0=A, 2=B, 4=C

    if (slot < 9) {
        const int bi = slot * 4 + warp;   // 0..35
        ph = bi / 6; pw = bi % 6;
    } else if (slot < 15) {
        const int e = (slot - 9) * 2 + (warp >> 1);   // 0..11
        half = warp & 1;
        if (e < 6) { ph = e; pw = 6; splitx = 1; }
        else       { ph = 6; pw = e - 6; splitx = 0; }
        split2 = 1; combine = 2;
    } else {
        ph = 6; pw = 6; combine = 4;
    }

    // bin ranges (clamped)
    int y0 = max(ys + ph * sth, 0);
    int y1 = min(ys + ((ph == PH - 1) ? lenh : (ph + 1) * sth), HD);
    int x0 = max(xs + pw * stw, 0);
    int x1 = min(xs + ((pw == PW - 1) ? lenw : (pw + 1) * stw), WD);

    if (split2) {
        if (splitx) { const int m = x0 + ((x1 - x0) >> 1); if (half) x0 = m; else x1 = m; }
        else        { const int m = y0 + ((y1 - y0) >> 1); if (half) y0 = m; else y1 = m; }
    } else if (combine == 4) {
        const int my = y0 + ((y1 - y0) >> 1);
        const int mx = x0 + ((x1 - x0) >> 1);
        if (warp & 2) y0 = my; else y1 = my;
        if (warp & 1) x0 = mx; else x1 = mx;
    }

    const int nx   = x1 - x0;
    const int npix = (y1 - y0) * nx;   // >= 1 for every piece (rois in-bounds)

    float4 acc = make_float4(-FLT_MAX, -FLT_MAX, -FLT_MAX, -FLT_MAX);

    // lane = 4-channel group; incremental pointer walk, UN loads in flight.
    const float4* base0 = (const float4*)(fmap + ((size_t)b * HD) * WD * CD)
                          + (y0 * WD + x0) * (CD / 4) + lane;
    const float4* p = base0;
    const int rowskip = (WD - nx) * (CD / 4);
    int xi = 0;

#define ADV { p += (CD / 4); if (++xi == nx) { xi = 0; p += rowskip; } }

    float4 buf[UN];
    int i = 0;
    for (; i + UN <= npix; i += UN) {
        #pragma unroll
        for (int k = 0; k < UN; k++) { buf[k] = __ldg(p); ADV }
        #pragma unroll
        for (int k = 0; k < UN; k++) fmax4(acc, buf[k]);
    }
    // batched tail: always issue UN loads; out-of-range slots re-load the
    // bin's first pixel (SEL on the address, no branch). fmax is idempotent,
    // so the duplicate contributions are free. Removes the serial remainder.
    {
        const int rem = npix - i;   // 0..UN-1
        if (rem) {
            #pragma unroll
            for (int k = 0; k < UN; k++) {
                const float4* q = (k < rem) ? p : base0;
                buf[k] = __ldg(q);
                ADV
            }
            #pragma unroll
            for (int k = 0; k < UN; k++) fmax4(acc, buf[k]);
        }
    }

    const int bin = (roi * PH + ph) * PW + pw;

    if (combine == 0) {
        ((float4*)out)[(size_t)bin * 32 + lane] = acc;
    } else {
        __shared__ float4 smax[4][32];
        smax[warp][lane] = acc;
        __syncthreads();
        if (combine == 4) {
            if (warp == 0) {
                float4 a = smax[0][lane];
                fmax4(a, smax[1][lane]);
                fmax4(a, smax[2][lane]);
                fmax4(a, smax[3][lane]);
                ((float4*)out)[(size_t)bin * 32 + lane] = a;
            }
        } else {
            if ((warp & 1) == 0) {
                float4 a = smax[warp][lane];
                fmax4(a, smax[warp + 1][lane]);
                ((float4*)out)[(size_t)bin * 32 + lane] = a;
            }
        }
    }
}

extern "C" void kernel_launch(void* const* d_in, const int* in_sizes, int n_in,
                              void* d_out, int out_size) {
    const float* fmap = (const float*)d_in[0];
    const float* rois = (const float*)d_in[1];
    float* out = (float*)d_out;
    roipool_kernel<<<NROI * 16, 128>>>(fmap, rois, out);
}

// round 16
// speedup vs baseline: 1.4505x; 1.3773x over previous
#include <cuda_runtime.h>
#include <float.h>

#define PH 7
#define PW 7
#define BD 2
#define ND 96
#define HD 64
#define WD 64
#define CD 128

#define NROI (BD * ND)              // 192
#define PXF4 (CD / 4)               // 32 float4 per pixel step
#define ROWF4 (WD * (CD / 4))       // 2048 float4 per row step

__device__ __forceinline__ void fmax4(float4& a, const float4& v) {
    a.x = fmaxf(a.x, v.x);
    a.y = fmaxf(a.y, v.y);
    a.z = fmaxf(a.z, v.z);
    a.w = fmaxf(a.w, v.w);
}

// 16 CTAs per ROI (same decomposition as the 10.75us R13 kernel):
//   slot 0..8  (A): 4 interior bins per CTA (warp-per-bin)
//   slot 9..14 (B): 2 edge bins per CTA, 2 warps each (long-axis halves)
//   slot 15    (C): corner bin, 4 warps (2x2 quadrants)
// After splitting, every piece is <=5 rows x <=5 cols -> nx-specialized
// row-batched loops with compile-time immediate offsets (no per-pixel ADV).
__global__ void __launch_bounds__(128)
roipool_kernel(const float* __restrict__ fmap,
               const float* __restrict__ rois,
               float* __restrict__ out) {
    const int warp = threadIdx.x >> 5;
    const int lane = threadIdx.x & 31;
    const int roi  = blockIdx.x >> 4;
    const int slot = blockIdx.x & 15;
    const int b    = roi / ND;

    // roi = [x_center, y_center, width, height]
    const float4 r4 = __ldg((const float4*)(rois) + roi);

    // y axis (yc, hh)
    const float halfh = floorf(r4.w * 0.5f);
    const int ys   = (int)(r4.y - halfh);
    const int lenh = (int)(r4.y + halfh) - ys;
    const int sth  = max(lenh / PH, 1);
    // x axis (xc, ww)
    const float halfw = floorf(r4.z * 0.5f);
    const int xs   = (int)(r4.x - halfw);
    const int lenw = (int)(r4.x + halfw) - xs;
    const int stw  = max(lenw / PW, 1);

    int ph, pw;
    int split2 = 0, half = 0;        // B: split along long axis
    int splitx = 0;                  // B: 1 = split x (pw==6), 0 = split y
    int combine = 0;                 // 0=A, 2=B, 4=C

    if (slot < 9) {
        const int bi = slot * 4 + warp;   // 0..35
        ph = bi / 6; pw = bi % 6;
    } else if (slot < 15) {
        const int e = (slot - 9) * 2 + (warp >> 1);   // 0..11
        half = warp & 1;
        if (e < 6) { ph = e; pw = 6; splitx = 1; }
        else       { ph = 6; pw = e - 6; splitx = 0; }
        split2 = 1; combine = 2;
    } else {
        ph = 6; pw = 6; combine = 4;
    }

    // bin ranges (clamped)
    int y0 = max(ys + ph * sth, 0);
    int y1 = min(ys + ((ph == PH - 1) ? lenh : (ph + 1) * sth), HD);
    int x0 = max(xs + pw * stw, 0);
    int x1 = min(xs + ((pw == PW - 1) ? lenw : (pw + 1) * stw), WD);

    if (split2) {
        if (splitx) { const int m = x0 + ((x1 - x0) >> 1); if (half) x0 = m; else x1 = m; }
        else        { const int m = y0 + ((y1 - y0) >> 1); if (half) y0 = m; else y1 = m; }
    } else if (combine == 4) {
        const int my = y0 + ((y1 - y0) >> 1);
        const int mx = x0 + ((x1 - x0) >> 1);
        if (warp & 2) y0 = my; else y1 = my;
        if (warp & 1) x0 = mx; else x1 = mx;
    }

    const int nx = x1 - x0;          // 1..5 by construction
    const int ny = y1 - y0;          // 1..5 by construction

    float4 acc = make_float4(-FLT_MAX, -FLT_MAX, -FLT_MAX, -FLT_MAX);

    // lane = 4-channel group; row-batched loads with immediate offsets.
    const float4* p = (const float4*)(fmap + ((size_t)b * HD) * WD * CD)
                      + (y0 * WD + x0) * PXF4 + lane;

    switch (nx) {
    case 1: {
        for (int r = ny; r > 0; --r, p += ROWF4) {
            float4 a0 = __ldg(p);
            fmax4(acc, a0);
        }
    } break;
    case 2: {
        int r = ny;
        for (; r >= 2; r -= 2, p += 2 * ROWF4) {
            float4 a0 = __ldg(p),          a1 = __ldg(p + PXF4);
            float4 b0 = __ldg(p + ROWF4),  b1 = __ldg(p + ROWF4 + PXF4);
            fmax4(acc, a0); fmax4(acc, a1);
            fmax4(acc, b0); fmax4(acc, b1);
        }
        if (r) {
            float4 a0 = __ldg(p), a1 = __ldg(p + PXF4);
            fmax4(acc, a0); fmax4(acc, a1);
        }
    } break;
    case 3: {
        int r = ny;
        for (; r >= 2; r -= 2, p += 2 * ROWF4) {
            float4 a0 = __ldg(p),         a1 = __ldg(p + PXF4),         a2 = __ldg(p + 2 * PXF4);
            float4 b0 = __ldg(p + ROWF4), b1 = __ldg(p + ROWF4 + PXF4), b2 = __ldg(p + ROWF4 + 2 * PXF4);
            fmax4(acc, a0); fmax4(acc, a1); fmax4(acc, a2);
            fmax4(acc, b0); fmax4(acc, b1); fmax4(acc, b2);
        }
        if (r) {
            float4 a0 = __ldg(p), a1 = __ldg(p + PXF4), a2 = __ldg(p + 2 * PXF4);
            fmax4(acc, a0); fmax4(acc, a1); fmax4(acc, a2);
        }
    } break;
    case 4: {
        int r = ny;
        for (; r >= 2; r -= 2, p += 2 * ROWF4) {
            float4 a0 = __ldg(p),         a1 = __ldg(p + PXF4);
            float4 a2 = __ldg(p + 2 * PXF4), a3 = __ldg(p + 3 * PXF4);
            float4 b0 = __ldg(p + ROWF4),    b1 = __ldg(p + ROWF4 + PXF4);
            float4 b2 = __ldg(p + ROWF4 + 2 * PXF4), b3 = __ldg(p + ROWF4 + 3 * PXF4);
            fmax4(acc, a0); fmax4(acc, a1); fmax4(acc, a2); fmax4(acc, a3);
            fmax4(acc, b0); fmax4(acc, b1); fmax4(acc, b2); fmax4(acc, b3);
        }
        if (r) {
            float4 a0 = __ldg(p),            a1 = __ldg(p + PXF4);
            float4 a2 = __ldg(p + 2 * PXF4), a3 = __ldg(p + 3 * PXF4);
            fmax4(acc, a0); fmax4(acc, a1); fmax4(acc, a2); fmax4(acc, a3);
        }
    } break;
    default: {  // nx == 5 (and safety for anything larger never produced)
        for (int r = ny; r > 0; --r, p += ROWF4) {
            float4 a0 = __ldg(p),            a1 = __ldg(p + PXF4);
            float4 a2 = __ldg(p + 2 * PXF4), a3 = __ldg(p + 3 * PXF4);
            float4 a4 = __ldg(p + 4 * PXF4);
            fmax4(acc, a0); fmax4(acc, a1); fmax4(acc, a2);
            fmax4(acc, a3); fmax4(acc, a4);
        }
    } break;
    }

    const int bin = (roi * PH + ph) * PW + pw;

    if (combine == 0) {
        ((float4*)out)[(size_t)bin * 32 + lane] = acc;
    } else {
        __shared__ float4 smax[4][32];
        smax[warp][lane] = acc;
        __syncthreads();
        if (combine == 4) {
            if (warp == 0) {
                float4 a = smax[0][lane];
                fmax4(a, smax[1][lane]);
                fmax4(a, smax[2][lane]);
                fmax4(a, smax[3][lane]);
                ((float4*)out)[(size_t)bin * 32 + lane] = a;
            }
        } else {
            if ((warp & 1) == 0) {
                float4 a = smax[warp][lane];
                fmax4(a, smax[warp + 1][lane]);
                ((float4*)out)[(size_t)bin * 32 + lane] = a;
            }
        }
    }
}

extern "C" void kernel_launch(void* const* d_in, const int* in_sizes, int n_in,
                              void* d_out, int out_size) {
    const float* fmap = (const float*)d_in[0];
    const float* rois = (const float*)d_in[1];
    float* out = (float*)d_out;
    roipool_kernel<<<NROI * 16, 128>>>(fmap, rois, out);
}